// round 13
// baseline (speedup 1.0000x reference)
#include <cuda_runtime.h>
#include <cstdint>

#define HID 256
#define NNODE 64
#define NGRAPH 128
#define NROWS 8192   /* NGRAPH*NNODE */
#define DIN 512
#define NHEAD 4
#define CH 64

// ---------------- scratch (no allocations allowed -> __device__ globals) ----
__device__ float g_h0[NROWS * HID];   // projected input (full indexing, sparse fill)
__device__ float g_hw[NROWS * HID];   // working hidden state (COMPACT rows)
__device__ float g_xl[NROWS * HID];   // compact
__device__ float g_xr[NROWS * HID];   // compact
__device__ float g_go[NROWS * HID];   // gat raw output (compact)
__device__ unsigned long long g_maskbits[NGRAPH];
__device__ int g_keep[NGRAPH];
__device__ int g_rowlist[NROWS];      // compact -> full row index (masked rows)
__device__ int g_goff[NGRAPH + 1];    // per-graph compact offsets
__device__ int g_total;               // total masked rows
__device__ int g_extlist[NROWS];      // masked rows + rows of non-keep graphs
__device__ int g_ext_total;

// ---------------- f32x2 packed math (Blackwell FFMA2, PTX-only) -------------
#define PACK2(u, lo, hi) asm("mov.b64 %0, {%1, %2};" : "=l"(u) : "f"(lo), "f"(hi))
#define UNPACK2(lo, hi, u) asm("mov.b64 {%0, %1}, %2;" : "=f"(lo), "=f"(hi) : "l"(u))
#define FMA2ACC(d, a, b) asm("fma.rn.f32x2 %0, %1, %2, %0;" : "+l"(d) : "l"(a), "l"(b))
#define ADD2(d, a, b) asm("add.rn.f32x2 %0, %1, %2;" : "=l"(d) : "l"(a), "l"(b))

// ---------------- mask decode + compaction (dtype-robust) -------------------
__global__ void decode_mask_kernel(const unsigned char* __restrict__ pm) {
    __shared__ int flags[4];
    __shared__ unsigned char sm[NROWS];
    __shared__ unsigned long long s_mb[NGRAPH];
    __shared__ int s_cnt[NGRAPH];
    __shared__ int s_off[NGRAPH];
    __shared__ int s_eoff[NGRAPH];
    int tid = threadIdx.x;
    if (tid < 4) flags[tid] = 0;
    __syncthreads();
    int loc0 = 0, loc1 = 0, loc23 = 0;
    for (int i = tid; i < NROWS; i += 256) {
        if (pm[i]) {
            int r = i & 3;
            if (r == 0) loc0 = 1;
            else if (r == 1) loc1 = 1;
            else loc23 = 1;
        }
    }
    if (loc0) atomicOr(&flags[0], 1);
    if (loc1) atomicOr(&flags[1], 1);
    if (loc23) atomicOr(&flags[2], 1);
    __syncthreads();
    int mode;
    if (flags[1]) mode = 0;          // uint8
    else if (flags[0]) mode = 1;     // int32
    else if (flags[2]) mode = 2;     // float32
    else mode = 0;
    for (int i = tid; i < NROWS; i += 256) {
        unsigned char m;
        if (mode == 0)      m = (pm[i] != 0);
        else if (mode == 1) m = (((const int*)pm)[i] != 0);
        else                m = (((const float*)pm)[i] != 0.0f);
        sm[i] = m;
    }
    __syncthreads();
    if (tid < NGRAPH) {
        unsigned long long mb = 0ull;
        int cnt = 0;
        #pragma unroll
        for (int n = 0; n < 64; n++) {
            if (sm[tid * 64 + n]) { mb |= (1ull << n); cnt++; }
        }
        s_mb[tid] = mb;
        s_cnt[tid] = cnt;
        g_maskbits[tid] = mb;
        g_keep[tid] = (cnt > 1) ? 1 : 0;
    }
    __syncthreads();
    if (tid == 0) {
        int acc = 0, eacc = 0;
        for (int g2 = 0; g2 < NGRAPH; g2++) {
            s_off[g2] = acc;
            g_goff[g2] = acc;
            acc += s_cnt[g2];
            s_eoff[g2] = eacc;
            eacc += (s_cnt[g2] > 1) ? s_cnt[g2] : 64;   // non-keep: all rows
        }
        g_goff[NGRAPH] = acc;
        g_total = acc;
        g_ext_total = eacc;
    }
    __syncthreads();
    if (tid < NGRAPH) {
        int off = s_off[tid];
        unsigned long long b = s_mb[tid];
        int base = tid << 6;
        while (b) {
            g_rowlist[off++] = base + (__ffsll(b) - 1);
            b &= b - 1;
        }
        int eoff = s_eoff[tid];
        if (s_cnt[tid] > 1) {
            unsigned long long b2 = s_mb[tid];
            while (b2) {
                g_extlist[eoff++] = base + (__ffsll(b2) - 1);
                b2 &= b2 - 1;
            }
        } else {
            for (int n = 0; n < 64; n++) g_extlist[eoff++] = base + n;
        }
    }
}

// ---------------- GEMM: 64x128 tile, 128 threads, BK=8, 8x8 microtile -------
// C[total,256] = gather(A)[*,K] @ W[K,256] + bias, optional scatter on C.
// Microtile columns: n = {tx*4..+3} and {64+tx*4..+3}  -> every LDS.128 phase
// reads one contiguous 128B smem row (conflict-free).
__global__ __launch_bounds__(128, 4) void gemm64_kernel(
    const float* __restrict__ A, const int* __restrict__ rowlist,
    const int* __restrict__ outlist, const int* __restrict__ totalp,
    const float* __restrict__ W0, const float* __restrict__ W1,
    const float* __restrict__ bias0, const float* __restrict__ bias1,
    float* __restrict__ C0, float* __restrict__ C1, int K) {
    __shared__ float As[2][8][68];    // padded: conflict-free transposed stores
    __shared__ float Bs[2][8][128];
    __shared__ int s_total;
    const int Nc = 256;
    int tid = threadIdx.x;
    if (tid == 0) s_total = totalp ? *totalp : NROWS;
    __syncthreads();
    int total = s_total;
    int bm = blockIdx.x << 6;
    if (bm >= total) return;

    int sel, bn;
    if (gridDim.y == 4) { sel = blockIdx.y >> 1; bn = (blockIdx.y & 1) << 7; }
    else               { sel = 0;               bn = blockIdx.y << 7; }
    const float* W = sel ? W1 : W0;
    const float* bias = sel ? bias1 : bias0;
    float* C = sel ? C1 : C0;

    int tx = tid & 15, ty = tid >> 4;
    int arow = tid >> 1, akq = (tid & 1) << 2;
    int r_glob = bm + arow;
    int ar = rowlist ? rowlist[min(r_glob, total - 1)] : r_glob;
    const float* Ag = A + (size_t)ar * K + akq;
    int brow0 = (tid >> 5) << 1, bcol = (tid & 31) << 2;
    const float* Bg = W + (size_t)brow0 * Nc + bn + bcol;

    unsigned long long acc[8][4];
    #pragma unroll
    for (int r = 0; r < 8; r++)
        #pragma unroll
        for (int p = 0; p < 4; p++) acc[r][p] = 0ull;

    // prologue: stage tile 0
    float4 ra = *(const float4*)Ag;
    float4 rb0 = *(const float4*)Bg;
    float4 rb1 = *(const float4*)(Bg + Nc);
    As[0][akq + 0][arow] = ra.x;
    As[0][akq + 1][arow] = ra.y;
    As[0][akq + 2][arow] = ra.z;
    As[0][akq + 3][arow] = ra.w;
    *(float4*)&Bs[0][brow0][bcol] = rb0;
    *(float4*)&Bs[0][brow0 + 1][bcol] = rb1;
    __syncthreads();

    int KB = K >> 3;
    int s = 0;
    for (int kb = 0; kb < KB; kb++) {
        if (kb + 1 < KB) {
            ra = *(const float4*)(Ag + ((kb + 1) << 3));
            rb0 = *(const float4*)(Bg + (size_t)((kb + 1) << 3) * Nc);
            rb1 = *(const float4*)(Bg + (size_t)((kb + 1) << 3) * Nc + Nc);
        }
        #pragma unroll
        for (int k = 0; k < 8; k++) {
            float4 a0 = *(const float4*)&As[s][k][ty << 3];
            float4 a1 = *(const float4*)&As[s][k][(ty << 3) + 4];
            float4 b0 = *(const float4*)&Bs[s][k][tx << 2];         // 128B row
            float4 b1 = *(const float4*)&Bs[s][k][64 + (tx << 2)];  // 128B row
            unsigned long long bp0, bp1, bp2, bp3;
            PACK2(bp0, b0.x, b0.y); PACK2(bp1, b0.z, b0.w);
            PACK2(bp2, b1.x, b1.y); PACK2(bp3, b1.z, b1.w);
            unsigned long long ad[8];
            PACK2(ad[0], a0.x, a0.x); PACK2(ad[1], a0.y, a0.y);
            PACK2(ad[2], a0.z, a0.z); PACK2(ad[3], a0.w, a0.w);
            PACK2(ad[4], a1.x, a1.x); PACK2(ad[5], a1.y, a1.y);
            PACK2(ad[6], a1.z, a1.z); PACK2(ad[7], a1.w, a1.w);
            #pragma unroll
            for (int r = 0; r < 8; r++) {
                FMA2ACC(acc[r][0], ad[r], bp0);
                FMA2ACC(acc[r][1], ad[r], bp1);
                FMA2ACC(acc[r][2], ad[r], bp2);
                FMA2ACC(acc[r][3], ad[r], bp3);
            }
        }
        if (kb + 1 < KB) {
            int sn = s ^ 1;
            As[sn][akq + 0][arow] = ra.x;
            As[sn][akq + 1][arow] = ra.y;
            As[sn][akq + 2][arow] = ra.z;
            As[sn][akq + 3][arow] = ra.w;
            *(float4*)&Bs[sn][brow0][bcol] = rb0;
            *(float4*)&Bs[sn][brow0 + 1][bcol] = rb1;
            __syncthreads();
            s = sn;
        }
    }

    float4 bb0 = *(const float4*)(bias + bn + (tx << 2));
    float4 bb1 = *(const float4*)(bias + bn + 64 + (tx << 2));
    #pragma unroll
    for (int r = 0; r < 8; r++) {
        int crow = bm + (ty << 3) + r;
        if (crow < total) {
            int orow = outlist ? outlist[crow] : crow;
            float* cp = C + (size_t)orow * Nc + bn;
            float4 o0, o1;
            UNPACK2(o0.x, o0.y, acc[r][0]); UNPACK2(o0.z, o0.w, acc[r][1]);
            UNPACK2(o1.x, o1.y, acc[r][2]); UNPACK2(o1.z, o1.w, acc[r][3]);
            o0.x += bb0.x; o0.y += bb0.y; o0.z += bb0.z; o0.w += bb0.w;
            o1.x += bb1.x; o1.y += bb1.y; o1.z += bb1.z; o1.w += bb1.w;
            *(float4*)(cp + (tx << 2)) = o0;
            *(float4*)(cp + 64 + (tx << 2)) = o1;
        }
    }
}

// ---------------- GATv2 attention on compact rows ---------------------------
// e_ij = 0.6*(a.xr_i + a.xl_j) + 0.4*sum_c a_c*|xr_i[c]+xl_j[c]|  (exact
// leaky_relu decomposition); rank-1 parts precomputed per node.
// alpha lives per-warp (produced+consumed in-iteration) -> smem ~37KB, occ 6.
__global__ __launch_bounds__(256) void attn_kernel(
    const float* __restrict__ xl, const float* __restrict__ xr,
    const float* __restrict__ att, float* __restrict__ go) {
    __shared__ float s_xlc[64 * 64];
    __shared__ float s_xrc[64 * 64];
    __shared__ float s_alpha[8][2][64];
    __shared__ float s_att[64];
    __shared__ float s_dl[64], s_dr[64];

    int g = blockIdx.x, h = blockIdx.y;
    int tid = threadIdx.x, w = tid >> 5, l = tid & 31;
    int goffg = g_goff[g];
    int M = g_goff[g + 1] - goffg;
    if (M == 0) return;
    int hoff = h << 6;

    if (tid < 64) s_att[tid] = att[hoff + tid];
    for (int idx = tid; idx < (M << 6); idx += 256) {
        int m = idx >> 6, c = idx & 63;
        size_t p = (size_t)(goffg + m) * HID + hoff + c;
        s_xlc[idx] = xl[p];
        s_xrc[idx] = xr[p];
    }
    __syncthreads();

    // per-node rank-1 dots (skewed c -> conflict-free)
    if (tid < M) {
        float dl = 0.f, dr = 0.f;
        #pragma unroll 8
        for (int t = 0; t < 64; t++) {
            int c = (t + tid) & 63;
            float a = s_att[c];
            dl = fmaf(a, s_xlc[(tid << 6) + c], dl);
            dr = fmaf(a, s_xrc[(tid << 6) + c], dr);
        }
        s_dl[tid] = dl;
        s_dr[tid] = dr;
    }
    __syncthreads();

    const unsigned long long ABS2 = 0x7FFFFFFF7FFFFFFFull;
    bool v1 = (l < M), v2 = (l + 32 < M);
    float dl1 = v1 ? s_dl[l] : 0.f;
    float dl2 = v2 ? s_dl[l + 32] : 0.f;

    // warp w owns rows mi % 8 == w; two rows per iter to share xl loads
    for (int mi0 = w; mi0 < M; mi0 += 16) {
        int miA = mi0;
        int miB = (mi0 + 8) & 63;        // may be dead: computed, discarded
        bool hasB = (mi0 + 8) < M;
        unsigned long long aA1 = 0ull, aA2 = 0ull, aB1 = 0ull, aB2 = 0ull;
        #pragma unroll 4
        for (int t = 0; t < 32; t++) {
            int c = ((t + l) & 31) << 1;   // skew -> conflict-free 64-bit LDS
            unsigned long long a2 = *(const unsigned long long*)&s_att[c];
            unsigned long long x1 = *(const unsigned long long*)&s_xlc[(l << 6) + c];
            unsigned long long x2 = *(const unsigned long long*)&s_xlc[((l + 32) << 6) + c];
            unsigned long long rA = *(const unsigned long long*)&s_xrc[(miA << 6) + c];
            unsigned long long rB = *(const unsigned long long*)&s_xrc[(miB << 6) + c];
            unsigned long long sA1, sA2, sB1, sB2;
            ADD2(sA1, rA, x1); ADD2(sA2, rA, x2);
            ADD2(sB1, rB, x1); ADD2(sB2, rB, x2);
            sA1 &= ABS2; sA2 &= ABS2; sB1 &= ABS2; sB2 &= ABS2;
            FMA2ACC(aA1, a2, sA1); FMA2ACC(aA2, a2, sA2);
            FMA2ACC(aB1, a2, sB1); FMA2ACC(aB2, a2, sB2);
        }
        float lo, hi;
        UNPACK2(lo, hi, aA1); float abA1 = lo + hi;
        UNPACK2(lo, hi, aA2); float abA2 = lo + hi;
        UNPACK2(lo, hi, aB1); float abB1 = lo + hi;
        UNPACK2(lo, hi, aB2); float abB2 = lo + hi;
        float drA = s_dr[miA];
        float drB = s_dr[miB];
        float eA1 = v1 ? fmaf(0.4f, abA1, 0.6f * (drA + dl1)) : -1e30f;
        float eA2 = v2 ? fmaf(0.4f, abA2, 0.6f * (drA + dl2)) : -1e30f;
        float eB1 = v1 ? fmaf(0.4f, abB1, 0.6f * (drB + dl1)) : -1e30f;
        float eB2 = v2 ? fmaf(0.4f, abB2, 0.6f * (drB + dl2)) : -1e30f;
        float mxA = fmaxf(eA1, eA2);
        float mxB = fmaxf(eB1, eB2);
        #pragma unroll
        for (int o = 16; o > 0; o >>= 1) {
            mxA = fmaxf(mxA, __shfl_xor_sync(0xffffffffu, mxA, o));
            mxB = fmaxf(mxB, __shfl_xor_sync(0xffffffffu, mxB, o));
        }
        float pA1 = expf(eA1 - mxA), pA2 = expf(eA2 - mxA);
        float pB1 = expf(eB1 - mxB), pB2 = expf(eB2 - mxB);
        float svA = pA1 + pA2, svB = pB1 + pB2;
        #pragma unroll
        for (int o = 16; o > 0; o >>= 1) {
            svA += __shfl_xor_sync(0xffffffffu, svA, o);
            svB += __shfl_xor_sync(0xffffffffu, svB, o);
        }
        float invA = 1.0f / svA, invB = 1.0f / svB;
        s_alpha[w][0][l] = pA1 * invA;
        s_alpha[w][0][l + 32] = pA2 * invA;
        s_alpha[w][1][l] = pB1 * invB;
        s_alpha[w][1][l + 32] = pB2 * invB;
        __syncwarp();

        float oA1 = 0.f, oA2 = 0.f, oB1 = 0.f, oB2 = 0.f;
        for (int mj = 0; mj < M; mj++) {
            float x1 = s_xlc[(mj << 6) + l];
            float x2 = s_xlc[(mj << 6) + l + 32];
            float alA = s_alpha[w][0][mj];
            float alB = s_alpha[w][1][mj];
            oA1 = fmaf(alA, x1, oA1);
            oA2 = fmaf(alA, x2, oA2);
            oB1 = fmaf(alB, x1, oB1);
            oB2 = fmaf(alB, x2, oB2);
        }
        size_t gA = (size_t)(goffg + miA) * HID + hoff;
        go[gA + l] = oA1;
        go[gA + l + 32] = oA2;
        if (hasB) {
            size_t gB = (size_t)(goffg + miB) * HID + hoff;
            go[gB + l] = oB1;
            go[gB + l + 32] = oB2;
        }
        __syncwarp();
    }
}

// ---------------- epilogue on full rows, compact data -----------------------
__device__ __forceinline__ float block_reduce_sum_256(float v, float* red, int tid) {
    __syncthreads();
    #pragma unroll
    for (int o = 16; o > 0; o >>= 1)
        v += __shfl_xor_sync(0xffffffffu, v, o);
    if ((tid & 31) == 0) red[tid >> 5] = v;
    __syncthreads();
    float tot = 0.f;
    #pragma unroll
    for (int i = 0; i < 8; i++) tot += red[i];
    return tot;
}

__global__ __launch_bounds__(256) void epilogue_kernel(
    const float* __restrict__ go_c, const float* __restrict__ hw_c_in,
    const float* __restrict__ h0,
    const float* __restrict__ ob, const float* __restrict__ lns,
    const float* __restrict__ lnb,
    float* __restrict__ hw_c_out, float* __restrict__ outp, int final_layer) {
    __shared__ float red[8];
    int row = blockIdx.x;
    int c = threadIdx.x;
    int g = row >> 6, node = row & 63;
    unsigned long long mb = g_maskbits[g];
    bool masked = (mb >> node) & 1ull;
    size_t fidx = (size_t)row * HID + c;

    if (final_layer && !g_keep[g]) { outp[fidx] = h0[fidx]; return; }
    if (!masked) {
        if (final_layer) outp[fidx] = 0.f;
        return;
    }
    int ci = g_goff[g] + (int)__popcll(mb & ((1ull << node) - 1ull));
    size_t cidx = (size_t)ci * HID + c;
    float v = go_c[cidx] + ob[c];
    v = (v > 0.f) ? v : expm1f(v);                 // ELU (alpha=1)
    float sum = block_reduce_sum_256(v, red, c);
    float mu = sum * (1.0f / 256.0f);
    float d = v - mu;
    float s2 = block_reduce_sum_256(d * d, red, c);
    float var = s2 * (1.0f / 256.0f);
    float resid = final_layer ? hw_c_in[cidx] : h0[fidx];
    float y = d * rsqrtf(var + 1e-5f) * lns[c] + lnb[c] + resid;
    if (final_layer) outp[fidx] = y;
    else hw_c_out[cidx] = y;
}

// ---------------- launch ----------------------------------------------------
extern "C" void kernel_launch(void* const* d_in, const int* in_sizes, int n_in,
                              void* d_out, int out_size) {
    (void)in_sizes; (void)n_in; (void)out_size;
    const float* x   = (const float*)d_in[0];
    const unsigned char* pm = (const unsigned char*)d_in[1];
    const float* W_in = (const float*)d_in[2];
    const float* b_in = (const float*)d_in[3];
    const float* Wl  = (const float*)d_in[4];
    const float* bl  = (const float*)d_in[5];
    const float* Wr  = (const float*)d_in[6];
    const float* br  = (const float*)d_in[7];
    const float* att = (const float*)d_in[8];
    const float* ob  = (const float*)d_in[9];
    const float* lns = (const float*)d_in[10];
    const float* lnb = (const float*)d_in[11];
    float* out = (float*)d_out;

    float *h0, *hw, *xl, *xr, *go;
    int *rowlist, *extlist, *totalp, *ext_totalp;
    cudaGetSymbolAddress((void**)&h0, g_h0);
    cudaGetSymbolAddress((void**)&hw, g_hw);
    cudaGetSymbolAddress((void**)&xl, g_xl);
    cudaGetSymbolAddress((void**)&xr, g_xr);
    cudaGetSymbolAddress((void**)&go, g_go);
    cudaGetSymbolAddress((void**)&rowlist, g_rowlist);
    cudaGetSymbolAddress((void**)&extlist, g_extlist);
    cudaGetSymbolAddress((void**)&totalp, g_total);
    cudaGetSymbolAddress((void**)&ext_totalp, g_ext_total);

    decode_mask_kernel<<<1, 256>>>(pm);

    // input projection: only rows that are ever read (masked + non-keep graphs)
    gemm64_kernel<<<dim3(NROWS / 64, 2), 128>>>(
        x, extlist, extlist, ext_totalp, W_in, W_in, b_in, b_in, h0, h0, DIN);

    for (int li = 0; li < 2; li++) {
        const float* hin = li ? hw : h0;                 // li=0: full+gather
        const int* rl = li ? nullptr : rowlist;          // li=1: compact direct
        gemm64_kernel<<<dim3(NROWS / 64, 4), 128>>>(
            hin, rl, nullptr, totalp, Wl + li * HID * HID, Wr + li * HID * HID,
            bl + li * HID, br + li * HID, xl, xr, HID);
        attn_kernel<<<dim3(NGRAPH, NHEAD), 256>>>(xl, xr, att + li * NHEAD * CH, go);
        epilogue_kernel<<<NROWS, 256>>>(go, hw, h0, ob + li * HID, lns + li * HID,
                                        lnb + li * HID, hw,
                                        (li == 1) ? out : nullptr, (li == 1) ? 1 : 0);
    }
}

// round 14
// speedup vs baseline: 1.0522x; 1.0522x over previous
#include <cuda_runtime.h>
#include <cstdint>

#define HID 256
#define NNODE 64
#define NGRAPH 128
#define NROWS 8192   /* NGRAPH*NNODE */
#define DIN 512
#define NHEAD 4
#define CH 64

// ---------------- scratch (no allocations allowed -> __device__ globals) ----
__device__ float g_h0[NROWS * HID];   // projected input (full indexing, sparse fill)
__device__ float g_hw[NROWS * HID];   // working hidden state (COMPACT rows)
__device__ float g_xl[NROWS * HID];   // compact
__device__ float g_xr[NROWS * HID];   // compact
__device__ float g_go[NROWS * HID];   // gat raw output (compact)
__device__ unsigned long long g_maskbits[NGRAPH];
__device__ int g_keep[NGRAPH];
__device__ int g_rowlist[NROWS];      // compact -> full row index (masked rows)
__device__ int g_goff[NGRAPH + 1];    // per-graph compact offsets
__device__ int g_total;               // total masked rows
__device__ int g_extlist[NROWS];      // masked rows + rows of non-keep graphs
__device__ int g_ext_total;

// ---------------- f32x2 packed math (Blackwell FFMA2, PTX-only) -------------
#define PACK2(u, lo, hi) asm("mov.b64 %0, {%1, %2};" : "=l"(u) : "f"(lo), "f"(hi))
#define UNPACK2(lo, hi, u) asm("mov.b64 {%0, %1}, %2;" : "=f"(lo), "=f"(hi) : "l"(u))
#define FMA2ACC(d, a, b) asm("fma.rn.f32x2 %0, %1, %2, %0;" : "+l"(d) : "l"(a), "l"(b))
#define ADD2(d, a, b) asm("add.rn.f32x2 %0, %1, %2;" : "=l"(d) : "l"(a), "l"(b))

// ---------------- mask decode + compaction (dtype-robust) -------------------
__global__ void decode_mask_kernel(const unsigned char* __restrict__ pm) {
    __shared__ int flags[4];
    __shared__ unsigned char sm[NROWS];
    __shared__ unsigned long long s_mb[NGRAPH];
    __shared__ int s_cnt[NGRAPH];
    __shared__ int s_off[NGRAPH];
    __shared__ int s_eoff[NGRAPH];
    int tid = threadIdx.x;
    if (tid < 4) flags[tid] = 0;
    __syncthreads();
    int loc0 = 0, loc1 = 0, loc23 = 0;
    for (int i = tid; i < NROWS; i += 256) {
        if (pm[i]) {
            int r = i & 3;
            if (r == 0) loc0 = 1;
            else if (r == 1) loc1 = 1;
            else loc23 = 1;
        }
    }
    if (loc0) atomicOr(&flags[0], 1);
    if (loc1) atomicOr(&flags[1], 1);
    if (loc23) atomicOr(&flags[2], 1);
    __syncthreads();
    int mode;
    if (flags[1]) mode = 0;          // uint8
    else if (flags[0]) mode = 1;     // int32
    else if (flags[2]) mode = 2;     // float32
    else mode = 0;
    for (int i = tid; i < NROWS; i += 256) {
        unsigned char m;
        if (mode == 0)      m = (pm[i] != 0);
        else if (mode == 1) m = (((const int*)pm)[i] != 0);
        else                m = (((const float*)pm)[i] != 0.0f);
        sm[i] = m;
    }
    __syncthreads();
    if (tid < NGRAPH) {
        unsigned long long mb = 0ull;
        int cnt = 0;
        #pragma unroll
        for (int n = 0; n < 64; n++) {
            if (sm[tid * 64 + n]) { mb |= (1ull << n); cnt++; }
        }
        s_mb[tid] = mb;
        s_cnt[tid] = cnt;
        g_maskbits[tid] = mb;
        g_keep[tid] = (cnt > 1) ? 1 : 0;
    }
    __syncthreads();
    if (tid == 0) {
        int acc = 0, eacc = 0;
        for (int g2 = 0; g2 < NGRAPH; g2++) {
            s_off[g2] = acc;
            g_goff[g2] = acc;
            acc += s_cnt[g2];
            s_eoff[g2] = eacc;
            eacc += (s_cnt[g2] > 1) ? s_cnt[g2] : 64;   // non-keep: all rows
        }
        g_goff[NGRAPH] = acc;
        g_total = acc;
        g_ext_total = eacc;
    }
    __syncthreads();
    if (tid < NGRAPH) {
        int off = s_off[tid];
        unsigned long long b = s_mb[tid];
        int base = tid << 6;
        while (b) {
            g_rowlist[off++] = base + (__ffsll(b) - 1);
            b &= b - 1;
        }
        int eoff = s_eoff[tid];
        if (s_cnt[tid] > 1) {
            unsigned long long b2 = s_mb[tid];
            while (b2) {
                g_extlist[eoff++] = base + (__ffsll(b2) - 1);
                b2 &= b2 - 1;
            }
        } else {
            for (int n = 0; n < 64; n++) g_extlist[eoff++] = base + n;
        }
    }
}

// ---------------- GEMM: 64x128 tile, 128 threads, BK=8, 8x8 microtile -------
// C[total,256] = gather(A)[*,K] @ W[K,256] + bias, optional scatter on C.
// Microtile columns: n = {tx*4..+3} and {64+tx*4..+3}  -> every LDS.128 phase
// reads one contiguous 128B smem row (conflict-free).
__global__ __launch_bounds__(128, 4) void gemm64_kernel(
    const float* __restrict__ A, const int* __restrict__ rowlist,
    const int* __restrict__ outlist, const int* __restrict__ totalp,
    const float* __restrict__ W0, const float* __restrict__ W1,
    const float* __restrict__ bias0, const float* __restrict__ bias1,
    float* __restrict__ C0, float* __restrict__ C1, int K) {
    __shared__ float As[2][8][68];    // padded: conflict-free transposed stores
    __shared__ float Bs[2][8][128];
    __shared__ int s_total;
    const int Nc = 256;
    int tid = threadIdx.x;
    if (tid == 0) s_total = totalp ? *totalp : NROWS;
    __syncthreads();
    int total = s_total;
    int bm = blockIdx.x << 6;
    if (bm >= total) return;

    int sel, bn;
    if (gridDim.y == 4) { sel = blockIdx.y >> 1; bn = (blockIdx.y & 1) << 7; }
    else               { sel = 0;               bn = blockIdx.y << 7; }
    const float* W = sel ? W1 : W0;
    const float* bias = sel ? bias1 : bias0;
    float* C = sel ? C1 : C0;

    int tx = tid & 15, ty = tid >> 4;
    int arow = tid >> 1, akq = (tid & 1) << 2;
    int r_glob = bm + arow;
    int ar = rowlist ? rowlist[min(r_glob, total - 1)] : r_glob;
    const float* Ag = A + (size_t)ar * K + akq;
    int brow0 = (tid >> 5) << 1, bcol = (tid & 31) << 2;
    const float* Bg = W + (size_t)brow0 * Nc + bn + bcol;

    unsigned long long acc[8][4];
    #pragma unroll
    for (int r = 0; r < 8; r++)
        #pragma unroll
        for (int p = 0; p < 4; p++) acc[r][p] = 0ull;

    // prologue: stage tile 0
    float4 ra = *(const float4*)Ag;
    float4 rb0 = *(const float4*)Bg;
    float4 rb1 = *(const float4*)(Bg + Nc);
    As[0][akq + 0][arow] = ra.x;
    As[0][akq + 1][arow] = ra.y;
    As[0][akq + 2][arow] = ra.z;
    As[0][akq + 3][arow] = ra.w;
    *(float4*)&Bs[0][brow0][bcol] = rb0;
    *(float4*)&Bs[0][brow0 + 1][bcol] = rb1;
    __syncthreads();

    int KB = K >> 3;
    int s = 0;
    for (int kb = 0; kb < KB; kb++) {
        if (kb + 1 < KB) {
            ra = *(const float4*)(Ag + ((kb + 1) << 3));
            rb0 = *(const float4*)(Bg + (size_t)((kb + 1) << 3) * Nc);
            rb1 = *(const float4*)(Bg + (size_t)((kb + 1) << 3) * Nc + Nc);
        }
        #pragma unroll
        for (int k = 0; k < 8; k++) {
            float4 a0 = *(const float4*)&As[s][k][ty << 3];
            float4 a1 = *(const float4*)&As[s][k][(ty << 3) + 4];
            float4 b0 = *(const float4*)&Bs[s][k][tx << 2];         // 128B row
            float4 b1 = *(const float4*)&Bs[s][k][64 + (tx << 2)];  // 128B row
            unsigned long long bp0, bp1, bp2, bp3;
            PACK2(bp0, b0.x, b0.y); PACK2(bp1, b0.z, b0.w);
            PACK2(bp2, b1.x, b1.y); PACK2(bp3, b1.z, b1.w);
            unsigned long long ad[8];
            PACK2(ad[0], a0.x, a0.x); PACK2(ad[1], a0.y, a0.y);
            PACK2(ad[2], a0.z, a0.z); PACK2(ad[3], a0.w, a0.w);
            PACK2(ad[4], a1.x, a1.x); PACK2(ad[5], a1.y, a1.y);
            PACK2(ad[6], a1.z, a1.z); PACK2(ad[7], a1.w, a1.w);
            #pragma unroll
            for (int r = 0; r < 8; r++) {
                FMA2ACC(acc[r][0], ad[r], bp0);
                FMA2ACC(acc[r][1], ad[r], bp1);
                FMA2ACC(acc[r][2], ad[r], bp2);
                FMA2ACC(acc[r][3], ad[r], bp3);
            }
        }
        if (kb + 1 < KB) {
            int sn = s ^ 1;
            As[sn][akq + 0][arow] = ra.x;
            As[sn][akq + 1][arow] = ra.y;
            As[sn][akq + 2][arow] = ra.z;
            As[sn][akq + 3][arow] = ra.w;
            *(float4*)&Bs[sn][brow0][bcol] = rb0;
            *(float4*)&Bs[sn][brow0 + 1][bcol] = rb1;
            __syncthreads();
            s = sn;
        }
    }

    float4 bb0 = *(const float4*)(bias + bn + (tx << 2));
    float4 bb1 = *(const float4*)(bias + bn + 64 + (tx << 2));
    #pragma unroll
    for (int r = 0; r < 8; r++) {
        int crow = bm + (ty << 3) + r;
        if (crow < total) {
            int orow = outlist ? outlist[crow] : crow;
            float* cp = C + (size_t)orow * Nc + bn;
            float4 o0, o1;
            UNPACK2(o0.x, o0.y, acc[r][0]); UNPACK2(o0.z, o0.w, acc[r][1]);
            UNPACK2(o1.x, o1.y, acc[r][2]); UNPACK2(o1.z, o1.w, acc[r][3]);
            o0.x += bb0.x; o0.y += bb0.y; o0.z += bb0.z; o0.w += bb0.w;
            o1.x += bb1.x; o1.y += bb1.y; o1.z += bb1.z; o1.w += bb1.w;
            *(float4*)(cp + (tx << 2)) = o0;
            *(float4*)(cp + 64 + (tx << 2)) = o1;
        }
    }
}

// ---------------- GATv2 attention on compact rows ---------------------------
// e_ij = 0.6*(a.xr_i + a.xl_j) + 0.4*sum_c a_c*|xr_i[c]+xl_j[c]|  (exact
// leaky_relu decomposition); rank-1 parts precomputed per node.
// alpha lives per-warp (produced+consumed in-iteration) -> smem ~37KB, occ 6.
__global__ __launch_bounds__(256) void attn_kernel(
    const float* __restrict__ xl, const float* __restrict__ xr,
    const float* __restrict__ att, float* __restrict__ go) {
    __shared__ float s_xlc[64 * 64];
    __shared__ float s_xrc[64 * 64];
    __shared__ float s_alpha[8][2][64];
    __shared__ float s_att[64];
    __shared__ float s_dl[64], s_dr[64];

    int g = blockIdx.x, h = blockIdx.y;
    int tid = threadIdx.x, w = tid >> 5, l = tid & 31;
    int goffg = g_goff[g];
    int M = g_goff[g + 1] - goffg;
    if (M == 0) return;
    int hoff = h << 6;

    if (tid < 64) s_att[tid] = att[hoff + tid];
    for (int idx = tid; idx < (M << 6); idx += 256) {
        int m = idx >> 6, c = idx & 63;
        size_t p = (size_t)(goffg + m) * HID + hoff + c;
        s_xlc[idx] = xl[p];
        s_xrc[idx] = xr[p];
    }
    __syncthreads();

    // per-node rank-1 dots (skewed c -> conflict-free)
    if (tid < M) {
        float dl = 0.f, dr = 0.f;
        #pragma unroll 8
        for (int t = 0; t < 64; t++) {
            int c = (t + tid) & 63;
            float a = s_att[c];
            dl = fmaf(a, s_xlc[(tid << 6) + c], dl);
            dr = fmaf(a, s_xrc[(tid << 6) + c], dr);
        }
        s_dl[tid] = dl;
        s_dr[tid] = dr;
    }
    __syncthreads();

    const unsigned long long ABS2 = 0x7FFFFFFF7FFFFFFFull;
    bool v1 = (l < M), v2 = (l + 32 < M);
    float dl1 = v1 ? s_dl[l] : 0.f;
    float dl2 = v2 ? s_dl[l + 32] : 0.f;

    // warp w owns rows mi % 8 == w; two rows per iter to share xl loads
    for (int mi0 = w; mi0 < M; mi0 += 16) {
        int miA = mi0;
        int miB = (mi0 + 8) & 63;        // may be dead: computed, discarded
        bool hasB = (mi0 + 8) < M;
        unsigned long long aA1 = 0ull, aA2 = 0ull, aB1 = 0ull, aB2 = 0ull;
        #pragma unroll 4
        for (int t = 0; t < 32; t++) {
            int c = ((t + l) & 31) << 1;   // skew -> conflict-free 64-bit LDS
            unsigned long long a2 = *(const unsigned long long*)&s_att[c];
            unsigned long long x1 = *(const unsigned long long*)&s_xlc[(l << 6) + c];
            unsigned long long x2 = *(const unsigned long long*)&s_xlc[((l + 32) << 6) + c];
            unsigned long long rA = *(const unsigned long long*)&s_xrc[(miA << 6) + c];
            unsigned long long rB = *(const unsigned long long*)&s_xrc[(miB << 6) + c];
            unsigned long long sA1, sA2, sB1, sB2;
            ADD2(sA1, rA, x1); ADD2(sA2, rA, x2);
            ADD2(sB1, rB, x1); ADD2(sB2, rB, x2);
            sA1 &= ABS2; sA2 &= ABS2; sB1 &= ABS2; sB2 &= ABS2;
            FMA2ACC(aA1, a2, sA1); FMA2ACC(aA2, a2, sA2);
            FMA2ACC(aB1, a2, sB1); FMA2ACC(aB2, a2, sB2);
        }
        float lo, hi;
        UNPACK2(lo, hi, aA1); float abA1 = lo + hi;
        UNPACK2(lo, hi, aA2); float abA2 = lo + hi;
        UNPACK2(lo, hi, aB1); float abB1 = lo + hi;
        UNPACK2(lo, hi, aB2); float abB2 = lo + hi;
        float drA = s_dr[miA];
        float drB = s_dr[miB];
        float eA1 = v1 ? fmaf(0.4f, abA1, 0.6f * (drA + dl1)) : -1e30f;
        float eA2 = v2 ? fmaf(0.4f, abA2, 0.6f * (drA + dl2)) : -1e30f;
        float eB1 = v1 ? fmaf(0.4f, abB1, 0.6f * (drB + dl1)) : -1e30f;
        float eB2 = v2 ? fmaf(0.4f, abB2, 0.6f * (drB + dl2)) : -1e30f;
        float mxA = fmaxf(eA1, eA2);
        float mxB = fmaxf(eB1, eB2);
        #pragma unroll
        for (int o = 16; o > 0; o >>= 1) {
            mxA = fmaxf(mxA, __shfl_xor_sync(0xffffffffu, mxA, o));
            mxB = fmaxf(mxB, __shfl_xor_sync(0xffffffffu, mxB, o));
        }
        float pA1 = expf(eA1 - mxA), pA2 = expf(eA2 - mxA);
        float pB1 = expf(eB1 - mxB), pB2 = expf(eB2 - mxB);
        float svA = pA1 + pA2, svB = pB1 + pB2;
        #pragma unroll
        for (int o = 16; o > 0; o >>= 1) {
            svA += __shfl_xor_sync(0xffffffffu, svA, o);
            svB += __shfl_xor_sync(0xffffffffu, svB, o);
        }
        float invA = 1.0f / svA, invB = 1.0f / svB;
        s_alpha[w][0][l] = pA1 * invA;
        s_alpha[w][0][l + 32] = pA2 * invA;
        s_alpha[w][1][l] = pB1 * invB;
        s_alpha[w][1][l + 32] = pB2 * invB;
        __syncwarp();

        float oA1 = 0.f, oA2 = 0.f, oB1 = 0.f, oB2 = 0.f;
        for (int mj = 0; mj < M; mj++) {
            float x1 = s_xlc[(mj << 6) + l];
            float x2 = s_xlc[(mj << 6) + l + 32];
            float alA = s_alpha[w][0][mj];
            float alB = s_alpha[w][1][mj];
            oA1 = fmaf(alA, x1, oA1);
            oA2 = fmaf(alA, x2, oA2);
            oB1 = fmaf(alB, x1, oB1);
            oB2 = fmaf(alB, x2, oB2);
        }
        size_t gA = (size_t)(goffg + miA) * HID + hoff;
        go[gA + l] = oA1;
        go[gA + l + 32] = oA2;
        if (hasB) {
            size_t gB = (size_t)(goffg + miB) * HID + hoff;
            go[gB + l] = oB1;
            go[gB + l + 32] = oB2;
        }
        __syncwarp();
    }
}

// ---------------- epilogue on full rows, compact data -----------------------
__device__ __forceinline__ float block_reduce_sum_256(float v, float* red, int tid) {
    __syncthreads();
    #pragma unroll
    for (int o = 16; o > 0; o >>= 1)
        v += __shfl_xor_sync(0xffffffffu, v, o);
    if ((tid & 31) == 0) red[tid >> 5] = v;
    __syncthreads();
    float tot = 0.f;
    #pragma unroll
    for (int i = 0; i < 8; i++) tot += red[i];
    return tot;
}

__global__ __launch_bounds__(256) void epilogue_kernel(
    const float* __restrict__ go_c, const float* __restrict__ hw_c_in,
    const float* __restrict__ h0,
    const float* __restrict__ ob, const float* __restrict__ lns,
    const float* __restrict__ lnb,
    float* __restrict__ hw_c_out, float* __restrict__ outp, int final_layer) {
    __shared__ float red[8];
    int row = blockIdx.x;
    int c = threadIdx.x;
    int g = row >> 6, node = row & 63;
    unsigned long long mb = g_maskbits[g];
    bool masked = (mb >> node) & 1ull;
    size_t fidx = (size_t)row * HID + c;

    if (final_layer && !g_keep[g]) { outp[fidx] = h0[fidx]; return; }
    if (!masked) {
        if (final_layer) outp[fidx] = 0.f;
        return;
    }
    int ci = g_goff[g] + (int)__popcll(mb & ((1ull << node) - 1ull));
    size_t cidx = (size_t)ci * HID + c;
    float v = go_c[cidx] + ob[c];
    v = (v > 0.f) ? v : expm1f(v);                 // ELU (alpha=1)
    float sum = block_reduce_sum_256(v, red, c);
    float mu = sum * (1.0f / 256.0f);
    float d = v - mu;
    float s2 = block_reduce_sum_256(d * d, red, c);
    float var = s2 * (1.0f / 256.0f);
    float resid = final_layer ? hw_c_in[cidx] : h0[fidx];
    float y = d * rsqrtf(var + 1e-5f) * lns[c] + lnb[c] + resid;
    if (final_layer) outp[fidx] = y;
    else hw_c_out[cidx] = y;
}

// ---------------- launch ----------------------------------------------------
extern "C" void kernel_launch(void* const* d_in, const int* in_sizes, int n_in,
                              void* d_out, int out_size) {
    (void)in_sizes; (void)n_in; (void)out_size;
    const float* x   = (const float*)d_in[0];
    const unsigned char* pm = (const unsigned char*)d_in[1];
    const float* W_in = (const float*)d_in[2];
    const float* b_in = (const float*)d_in[3];
    const float* Wl  = (const float*)d_in[4];
    const float* bl  = (const float*)d_in[5];
    const float* Wr  = (const float*)d_in[6];
    const float* br  = (const float*)d_in[7];
    const float* att = (const float*)d_in[8];
    const float* ob  = (const float*)d_in[9];
    const float* lns = (const float*)d_in[10];
    const float* lnb = (const float*)d_in[11];
    float* out = (float*)d_out;

    float *h0, *hw, *xl, *xr, *go;
    int *rowlist, *extlist, *totalp, *ext_totalp;
    cudaGetSymbolAddress((void**)&h0, g_h0);
    cudaGetSymbolAddress((void**)&hw, g_hw);
    cudaGetSymbolAddress((void**)&xl, g_xl);
    cudaGetSymbolAddress((void**)&xr, g_xr);
    cudaGetSymbolAddress((void**)&go, g_go);
    cudaGetSymbolAddress((void**)&rowlist, g_rowlist);
    cudaGetSymbolAddress((void**)&extlist, g_extlist);
    cudaGetSymbolAddress((void**)&totalp, g_total);
    cudaGetSymbolAddress((void**)&ext_totalp, g_ext_total);

    decode_mask_kernel<<<1, 256>>>(pm);

    // input projection: only rows that are ever read (masked + non-keep graphs)
    gemm64_kernel<<<dim3(NROWS / 64, 2), 128>>>(
        x, extlist, extlist, ext_totalp, W_in, W_in, b_in, b_in, h0, h0, DIN);

    for (int li = 0; li < 2; li++) {
        const float* hin = li ? hw : h0;                 // li=0: full+gather
        const int* rl = li ? nullptr : rowlist;          // li=1: compact direct
        gemm64_kernel<<<dim3(NROWS / 64, 4), 128>>>(
            hin, rl, nullptr, totalp, Wl + li * HID * HID, Wr + li * HID * HID,
            bl + li * HID, br + li * HID, xl, xr, HID);
        attn_kernel<<<dim3(NGRAPH, NHEAD), 256>>>(xl, xr, att + li * NHEAD * CH, go);
        epilogue_kernel<<<NROWS, 256>>>(go, hw, h0, ob + li * HID, lns + li * HID,
                                        lnb + li * HID, hw,
                                        (li == 1) ? out : nullptr, (li == 1) ? 1 : 0);
    }
}

// round 15
// speedup vs baseline: 1.0919x; 1.0378x over previous
#include <cuda_runtime.h>
#include <cstdint>

#define HID 256
#define NNODE 64
#define NGRAPH 128
#define NROWS 8192   /* NGRAPH*NNODE */
#define DIN 512
#define NHEAD 4
#define CH 64

// ---------------- scratch (no allocations allowed -> __device__ globals) ----
__device__ float g_h0[NROWS * HID];   // projected input (full indexing, sparse fill)
__device__ float g_hw[NROWS * HID];   // working hidden state (COMPACT rows)
__device__ float g_xl[NROWS * HID];   // compact
__device__ float g_xr[NROWS * HID];   // compact
__device__ float g_go[NROWS * HID];   // gat raw output (compact)
__device__ unsigned long long g_maskbits[NGRAPH];
__device__ int g_keep[NGRAPH];
__device__ int g_rowlist[NROWS];      // compact -> full row index (masked rows)
__device__ int g_goff[NGRAPH + 1];    // per-graph compact offsets
__device__ int g_total;               // total masked rows
__device__ int g_extlist[NROWS];      // masked rows + rows of non-keep graphs
__device__ int g_ext_total;

// ---------------- f32x2 packed math (Blackwell FFMA2, PTX-only) -------------
#define PACK2(u, lo, hi) asm("mov.b64 %0, {%1, %2};" : "=l"(u) : "f"(lo), "f"(hi))
#define UNPACK2(lo, hi, u) asm("mov.b64 {%0, %1}, %2;" : "=f"(lo), "=f"(hi) : "l"(u))
#define FMA2ACC(d, a, b) asm("fma.rn.f32x2 %0, %1, %2, %0;" : "+l"(d) : "l"(a), "l"(b))
#define ADD2(d, a, b) asm("add.rn.f32x2 %0, %1, %2;" : "=l"(d) : "l"(a), "l"(b))

// ---------------- mask decode + compaction (dtype-robust) -------------------
__global__ void decode_mask_kernel(const unsigned char* __restrict__ pm) {
    __shared__ int flags[4];
    __shared__ unsigned char sm[NROWS];
    __shared__ unsigned long long s_mb[NGRAPH];
    __shared__ int s_cnt[NGRAPH];
    __shared__ int s_off[NGRAPH];
    __shared__ int s_eoff[NGRAPH];
    int tid = threadIdx.x;
    if (tid < 4) flags[tid] = 0;
    __syncthreads();
    int loc0 = 0, loc1 = 0, loc23 = 0;
    for (int i = tid; i < NROWS; i += 256) {
        if (pm[i]) {
            int r = i & 3;
            if (r == 0) loc0 = 1;
            else if (r == 1) loc1 = 1;
            else loc23 = 1;
        }
    }
    if (loc0) atomicOr(&flags[0], 1);
    if (loc1) atomicOr(&flags[1], 1);
    if (loc23) atomicOr(&flags[2], 1);
    __syncthreads();
    int mode;
    if (flags[1]) mode = 0;          // uint8
    else if (flags[0]) mode = 1;     // int32
    else if (flags[2]) mode = 2;     // float32
    else mode = 0;
    for (int i = tid; i < NROWS; i += 256) {
        unsigned char m;
        if (mode == 0)      m = (pm[i] != 0);
        else if (mode == 1) m = (((const int*)pm)[i] != 0);
        else                m = (((const float*)pm)[i] != 0.0f);
        sm[i] = m;
    }
    __syncthreads();
    if (tid < NGRAPH) {
        unsigned long long mb = 0ull;
        int cnt = 0;
        #pragma unroll
        for (int n = 0; n < 64; n++) {
            if (sm[tid * 64 + n]) { mb |= (1ull << n); cnt++; }
        }
        s_mb[tid] = mb;
        s_cnt[tid] = cnt;
        g_maskbits[tid] = mb;
        g_keep[tid] = (cnt > 1) ? 1 : 0;
    }
    __syncthreads();
    if (tid == 0) {
        int acc = 0, eacc = 0;
        for (int g2 = 0; g2 < NGRAPH; g2++) {
            s_off[g2] = acc;
            g_goff[g2] = acc;
            acc += s_cnt[g2];
            s_eoff[g2] = eacc;
            eacc += (s_cnt[g2] > 1) ? s_cnt[g2] : 64;   // non-keep: all rows
        }
        g_goff[NGRAPH] = acc;
        g_total = acc;
        g_ext_total = eacc;
    }
    __syncthreads();
    if (tid < NGRAPH) {
        int off = s_off[tid];
        unsigned long long b = s_mb[tid];
        int base = tid << 6;
        while (b) {
            g_rowlist[off++] = base + (__ffsll(b) - 1);
            b &= b - 1;
        }
        int eoff = s_eoff[tid];
        if (s_cnt[tid] > 1) {
            unsigned long long b2 = s_mb[tid];
            while (b2) {
                g_extlist[eoff++] = base + (__ffsll(b2) - 1);
                b2 &= b2 - 1;
            }
        } else {
            for (int n = 0; n < 64; n++) g_extlist[eoff++] = base + n;
        }
    }
}

// ---------------- GEMM: 64x128 tile, 128 threads, BK=8, 8x8 microtile -------
// (unchanged from R6 — conflict-free B columns, balanced 8:1 FFMA2:LDS)
__global__ __launch_bounds__(128, 4) void gemm64_kernel(
    const float* __restrict__ A, const int* __restrict__ rowlist,
    const int* __restrict__ outlist, const int* __restrict__ totalp,
    const float* __restrict__ W0, const float* __restrict__ W1,
    const float* __restrict__ bias0, const float* __restrict__ bias1,
    float* __restrict__ C0, float* __restrict__ C1, int K) {
    __shared__ float As[2][8][68];
    __shared__ float Bs[2][8][128];
    __shared__ int s_total;
    const int Nc = 256;
    int tid = threadIdx.x;
    if (tid == 0) s_total = totalp ? *totalp : NROWS;
    __syncthreads();
    int total = s_total;
    int bm = blockIdx.x << 6;
    if (bm >= total) return;

    int sel, bn;
    if (gridDim.y == 4) { sel = blockIdx.y >> 1; bn = (blockIdx.y & 1) << 7; }
    else               { sel = 0;               bn = blockIdx.y << 7; }
    const float* W = sel ? W1 : W0;
    const float* bias = sel ? bias1 : bias0;
    float* C = sel ? C1 : C0;

    int tx = tid & 15, ty = tid >> 4;
    int arow = tid >> 1, akq = (tid & 1) << 2;
    int r_glob = bm + arow;
    int ar = rowlist ? rowlist[min(r_glob, total - 1)] : r_glob;
    const float* Ag = A + (size_t)ar * K + akq;
    int brow0 = (tid >> 5) << 1, bcol = (tid & 31) << 2;
    const float* Bg = W + (size_t)brow0 * Nc + bn + bcol;

    unsigned long long acc[8][4];
    #pragma unroll
    for (int r = 0; r < 8; r++)
        #pragma unroll
        for (int p = 0; p < 4; p++) acc[r][p] = 0ull;

    float4 ra = *(const float4*)Ag;
    float4 rb0 = *(const float4*)Bg;
    float4 rb1 = *(const float4*)(Bg + Nc);
    As[0][akq + 0][arow] = ra.x;
    As[0][akq + 1][arow] = ra.y;
    As[0][akq + 2][arow] = ra.z;
    As[0][akq + 3][arow] = ra.w;
    *(float4*)&Bs[0][brow0][bcol] = rb0;
    *(float4*)&Bs[0][brow0 + 1][bcol] = rb1;
    __syncthreads();

    int KB = K >> 3;
    int s = 0;
    for (int kb = 0; kb < KB; kb++) {
        if (kb + 1 < KB) {
            ra = *(const float4*)(Ag + ((kb + 1) << 3));
            rb0 = *(const float4*)(Bg + (size_t)((kb + 1) << 3) * Nc);
            rb1 = *(const float4*)(Bg + (size_t)((kb + 1) << 3) * Nc + Nc);
        }
        #pragma unroll
        for (int k = 0; k < 8; k++) {
            float4 a0 = *(const float4*)&As[s][k][ty << 3];
            float4 a1 = *(const float4*)&As[s][k][(ty << 3) + 4];
            float4 b0 = *(const float4*)&Bs[s][k][tx << 2];
            float4 b1 = *(const float4*)&Bs[s][k][64 + (tx << 2)];
            unsigned long long bp0, bp1, bp2, bp3;
            PACK2(bp0, b0.x, b0.y); PACK2(bp1, b0.z, b0.w);
            PACK2(bp2, b1.x, b1.y); PACK2(bp3, b1.z, b1.w);
            unsigned long long ad[8];
            PACK2(ad[0], a0.x, a0.x); PACK2(ad[1], a0.y, a0.y);
            PACK2(ad[2], a0.z, a0.z); PACK2(ad[3], a0.w, a0.w);
            PACK2(ad[4], a1.x, a1.x); PACK2(ad[5], a1.y, a1.y);
            PACK2(ad[6], a1.z, a1.z); PACK2(ad[7], a1.w, a1.w);
            #pragma unroll
            for (int r = 0; r < 8; r++) {
                FMA2ACC(acc[r][0], ad[r], bp0);
                FMA2ACC(acc[r][1], ad[r], bp1);
                FMA2ACC(acc[r][2], ad[r], bp2);
                FMA2ACC(acc[r][3], ad[r], bp3);
            }
        }
        if (kb + 1 < KB) {
            int sn = s ^ 1;
            As[sn][akq + 0][arow] = ra.x;
            As[sn][akq + 1][arow] = ra.y;
            As[sn][akq + 2][arow] = ra.z;
            As[sn][akq + 3][arow] = ra.w;
            *(float4*)&Bs[sn][brow0][bcol] = rb0;
            *(float4*)&Bs[sn][brow0 + 1][bcol] = rb1;
            __syncthreads();
            s = sn;
        }
    }

    float4 bb0 = *(const float4*)(bias + bn + (tx << 2));
    float4 bb1 = *(const float4*)(bias + bn + 64 + (tx << 2));
    #pragma unroll
    for (int r = 0; r < 8; r++) {
        int crow = bm + (ty << 3) + r;
        if (crow < total) {
            int orow = outlist ? outlist[crow] : crow;
            float* cp = C + (size_t)orow * Nc + bn;
            float4 o0, o1;
            UNPACK2(o0.x, o0.y, acc[r][0]); UNPACK2(o0.z, o0.w, acc[r][1]);
            UNPACK2(o1.x, o1.y, acc[r][2]); UNPACK2(o1.z, o1.w, acc[r][3]);
            o0.x += bb0.x; o0.y += bb0.y; o0.z += bb0.z; o0.w += bb0.w;
            o1.x += bb1.x; o1.y += bb1.y; o1.z += bb1.z; o1.w += bb1.w;
            *(float4*)(cp + (tx << 2)) = o0;
            *(float4*)(cp + 64 + (tx << 2)) = o1;
        }
    }
}

// ---------------- GATv2 attention, z-split x2 over target rows --------------
// grid (NGRAPH, NHEAD, 2): 16 virtual warps own rows mi === vw (mod 16),
// pairs (mi0, mi0+16), stride 32. float4 tile loads.
__global__ __launch_bounds__(256) void attn_kernel(
    const float* __restrict__ xl, const float* __restrict__ xr,
    const float* __restrict__ att, float* __restrict__ go) {
    __shared__ float s_xlc[64 * 64];
    __shared__ float s_xrc[64 * 64];
    __shared__ float s_alpha[8][2][64];
    __shared__ float s_att[64];
    __shared__ float s_dl[64], s_dr[64];

    int g = blockIdx.x, h = blockIdx.y;
    int tid = threadIdx.x, w = tid >> 5, l = tid & 31;
    int vw = (blockIdx.z << 3) + w;   // 0..15
    int goffg = g_goff[g];
    int M = g_goff[g + 1] - goffg;
    if (M == 0) return;
    int hoff = h << 6;

    if (tid < 64) s_att[tid] = att[hoff + tid];
    for (int idx4 = tid; idx4 < (M << 4); idx4 += 256) {
        int m = idx4 >> 4, c4 = (idx4 & 15) << 2;
        size_t p = (size_t)(goffg + m) * HID + hoff + c4;
        *(float4*)&s_xlc[(m << 6) + c4] = *(const float4*)(xl + p);
        *(float4*)&s_xrc[(m << 6) + c4] = *(const float4*)(xr + p);
    }
    __syncthreads();

    // per-node rank-1 dots (skewed c -> conflict-free)
    if (tid < M) {
        float dl = 0.f, dr = 0.f;
        #pragma unroll 8
        for (int t = 0; t < 64; t++) {
            int c = (t + tid) & 63;
            float a = s_att[c];
            dl = fmaf(a, s_xlc[(tid << 6) + c], dl);
            dr = fmaf(a, s_xrc[(tid << 6) + c], dr);
        }
        s_dl[tid] = dl;
        s_dr[tid] = dr;
    }
    __syncthreads();

    const unsigned long long ABS2 = 0x7FFFFFFF7FFFFFFFull;
    bool v1 = (l < M), v2 = (l + 32 < M);
    float dl1 = v1 ? s_dl[l] : 0.f;
    float dl2 = v2 ? s_dl[l + 32] : 0.f;

    for (int mi0 = vw; mi0 < M; mi0 += 32) {
        int miA = mi0;
        int miB = (mi0 + 16) & 63;       // may be dead: computed, discarded
        bool hasB = (mi0 + 16) < M;
        unsigned long long aA1 = 0ull, aA2 = 0ull, aB1 = 0ull, aB2 = 0ull;
        #pragma unroll 4
        for (int t = 0; t < 32; t++) {
            int c = ((t + l) & 31) << 1;   // skew -> conflict-free 64-bit LDS
            unsigned long long a2 = *(const unsigned long long*)&s_att[c];
            unsigned long long x1 = *(const unsigned long long*)&s_xlc[(l << 6) + c];
            unsigned long long x2 = *(const unsigned long long*)&s_xlc[((l + 32) << 6) + c];
            unsigned long long rA = *(const unsigned long long*)&s_xrc[(miA << 6) + c];
            unsigned long long rB = *(const unsigned long long*)&s_xrc[(miB << 6) + c];
            unsigned long long sA1, sA2, sB1, sB2;
            ADD2(sA1, rA, x1); ADD2(sA2, rA, x2);
            ADD2(sB1, rB, x1); ADD2(sB2, rB, x2);
            sA1 &= ABS2; sA2 &= ABS2; sB1 &= ABS2; sB2 &= ABS2;
            FMA2ACC(aA1, a2, sA1); FMA2ACC(aA2, a2, sA2);
            FMA2ACC(aB1, a2, sB1); FMA2ACC(aB2, a2, sB2);
        }
        float lo, hi;
        UNPACK2(lo, hi, aA1); float abA1 = lo + hi;
        UNPACK2(lo, hi, aA2); float abA2 = lo + hi;
        UNPACK2(lo, hi, aB1); float abB1 = lo + hi;
        UNPACK2(lo, hi, aB2); float abB2 = lo + hi;
        float drA = s_dr[miA];
        float drB = s_dr[miB];
        float eA1 = v1 ? fmaf(0.4f, abA1, 0.6f * (drA + dl1)) : -1e30f;
        float eA2 = v2 ? fmaf(0.4f, abA2, 0.6f * (drA + dl2)) : -1e30f;
        float eB1 = v1 ? fmaf(0.4f, abB1, 0.6f * (drB + dl1)) : -1e30f;
        float eB2 = v2 ? fmaf(0.4f, abB2, 0.6f * (drB + dl2)) : -1e30f;
        float mxA = fmaxf(eA1, eA2);
        float mxB = fmaxf(eB1, eB2);
        #pragma unroll
        for (int o = 16; o > 0; o >>= 1) {
            mxA = fmaxf(mxA, __shfl_xor_sync(0xffffffffu, mxA, o));
            mxB = fmaxf(mxB, __shfl_xor_sync(0xffffffffu, mxB, o));
        }
        float pA1 = expf(eA1 - mxA), pA2 = expf(eA2 - mxA);
        float pB1 = expf(eB1 - mxB), pB2 = expf(eB2 - mxB);
        float svA = pA1 + pA2, svB = pB1 + pB2;
        #pragma unroll
        for (int o = 16; o > 0; o >>= 1) {
            svA += __shfl_xor_sync(0xffffffffu, svA, o);
            svB += __shfl_xor_sync(0xffffffffu, svB, o);
        }
        float invA = 1.0f / svA, invB = 1.0f / svB;
        s_alpha[w][0][l] = pA1 * invA;
        s_alpha[w][0][l + 32] = pA2 * invA;
        s_alpha[w][1][l] = pB1 * invB;
        s_alpha[w][1][l + 32] = pB2 * invB;
        __syncwarp();

        float oA1 = 0.f, oA2 = 0.f, oB1 = 0.f, oB2 = 0.f;
        for (int mj = 0; mj < M; mj++) {
            float x1 = s_xlc[(mj << 6) + l];
            float x2 = s_xlc[(mj << 6) + l + 32];
            float alA = s_alpha[w][0][mj];
            float alB = s_alpha[w][1][mj];
            oA1 = fmaf(alA, x1, oA1);
            oA2 = fmaf(alA, x2, oA2);
            oB1 = fmaf(alB, x1, oB1);
            oB2 = fmaf(alB, x2, oB2);
        }
        size_t gA = (size_t)(goffg + miA) * HID + hoff;
        go[gA + l] = oA1;
        go[gA + l + 32] = oA2;
        if (hasB) {
            size_t gB = (size_t)(goffg + miB) * HID + hoff;
            go[gB + l] = oB1;
            go[gB + l + 32] = oB2;
        }
        __syncwarp();
    }
}

// ---------------- epilogue: warp-per-row, shfl-only LN ----------------------
__device__ __forceinline__ float warp_sum(float v) {
    #pragma unroll
    for (int o = 16; o > 0; o >>= 1)
        v += __shfl_xor_sync(0xffffffffu, v, o);
    return v;
}

__global__ __launch_bounds__(256) void epilogue_kernel(
    const float* __restrict__ go_c, const float* __restrict__ hw_c_in,
    const float* __restrict__ h0,
    const float* __restrict__ ob, const float* __restrict__ lns,
    const float* __restrict__ lnb,
    float* __restrict__ hw_c_out, float* __restrict__ outp, int final_layer) {
    int tid = threadIdx.x;
    int w = tid >> 5, l = tid & 31;
    int row = (blockIdx.x << 3) + w;     // full row, one warp each
    int g = row >> 6, node = row & 63;
    unsigned long long mb = g_maskbits[g];
    bool masked = (mb >> node) & 1ull;
    int cb = l << 3;                     // 8 channels per lane
    size_t fbase = (size_t)row * HID + cb;

    if (final_layer && !g_keep[g]) {
        *(float4*)(outp + fbase) = *(const float4*)(h0 + fbase);
        *(float4*)(outp + fbase + 4) = *(const float4*)(h0 + fbase + 4);
        return;
    }
    if (!masked) {
        if (final_layer) {
            float4 z = make_float4(0.f, 0.f, 0.f, 0.f);
            *(float4*)(outp + fbase) = z;
            *(float4*)(outp + fbase + 4) = z;
        }
        return;
    }
    int ci = g_goff[g] + (int)__popcll(mb & ((1ull << node) - 1ull));
    size_t cbase = (size_t)ci * HID + cb;

    float v[8];
    {
        float4 g0 = *(const float4*)(go_c + cbase);
        float4 g1 = *(const float4*)(go_c + cbase + 4);
        float4 o0 = *(const float4*)(ob + cb);
        float4 o1 = *(const float4*)(ob + cb + 4);
        v[0] = g0.x + o0.x; v[1] = g0.y + o0.y;
        v[2] = g0.z + o0.z; v[3] = g0.w + o0.w;
        v[4] = g1.x + o1.x; v[5] = g1.y + o1.y;
        v[6] = g1.z + o1.z; v[7] = g1.w + o1.w;
    }
    #pragma unroll
    for (int i = 0; i < 8; i++)
        v[i] = (v[i] > 0.f) ? v[i] : expm1f(v[i]);     // ELU (alpha=1)

    float loc = 0.f;
    #pragma unroll
    for (int i = 0; i < 8; i++) loc += v[i];
    float mu = warp_sum(loc) * (1.0f / 256.0f);

    float d[8], s2 = 0.f;
    #pragma unroll
    for (int i = 0; i < 8; i++) { d[i] = v[i] - mu; s2 = fmaf(d[i], d[i], s2); }
    float var = warp_sum(s2) * (1.0f / 256.0f);
    float rstd = rsqrtf(var + 1e-5f);

    float4 s0 = *(const float4*)(lns + cb);
    float4 s1 = *(const float4*)(lns + cb + 4);
    float4 b0 = *(const float4*)(lnb + cb);
    float4 b1 = *(const float4*)(lnb + cb + 4);
    float4 r0, r1;
    if (final_layer) {
        r0 = *(const float4*)(hw_c_in + cbase);
        r1 = *(const float4*)(hw_c_in + cbase + 4);
    } else {
        r0 = *(const float4*)(h0 + fbase);
        r1 = *(const float4*)(h0 + fbase + 4);
    }
    float4 y0, y1;
    y0.x = fmaf(d[0] * rstd, s0.x, b0.x) + r0.x;
    y0.y = fmaf(d[1] * rstd, s0.y, b0.y) + r0.y;
    y0.z = fmaf(d[2] * rstd, s0.z, b0.z) + r0.z;
    y0.w = fmaf(d[3] * rstd, s0.w, b0.w) + r0.w;
    y1.x = fmaf(d[4] * rstd, s1.x, b1.x) + r1.x;
    y1.y = fmaf(d[5] * rstd, s1.y, b1.y) + r1.y;
    y1.z = fmaf(d[6] * rstd, s1.z, b1.z) + r1.z;
    y1.w = fmaf(d[7] * rstd, s1.w, b1.w) + r1.w;
    if (final_layer) {
        *(float4*)(outp + fbase) = y0;
        *(float4*)(outp + fbase + 4) = y1;
    } else {
        *(float4*)(hw_c_out + cbase) = y0;
        *(float4*)(hw_c_out + cbase + 4) = y1;
    }
}

// ---------------- launch ----------------------------------------------------
extern "C" void kernel_launch(void* const* d_in, const int* in_sizes, int n_in,
                              void* d_out, int out_size) {
    (void)in_sizes; (void)n_in; (void)out_size;
    const float* x   = (const float*)d_in[0];
    const unsigned char* pm = (const unsigned char*)d_in[1];
    const float* W_in = (const float*)d_in[2];
    const float* b_in = (const float*)d_in[3];
    const float* Wl  = (const float*)d_in[4];
    const float* bl  = (const float*)d_in[5];
    const float* Wr  = (const float*)d_in[6];
    const float* br  = (const float*)d_in[7];
    const float* att = (const float*)d_in[8];
    const float* ob  = (const float*)d_in[9];
    const float* lns = (const float*)d_in[10];
    const float* lnb = (const float*)d_in[11];
    float* out = (float*)d_out;

    float *h0, *hw, *xl, *xr, *go;
    int *rowlist, *extlist, *totalp, *ext_totalp;
    cudaGetSymbolAddress((void**)&h0, g_h0);
    cudaGetSymbolAddress((void**)&hw, g_hw);
    cudaGetSymbolAddress((void**)&xl, g_xl);
    cudaGetSymbolAddress((void**)&xr, g_xr);
    cudaGetSymbolAddress((void**)&go, g_go);
    cudaGetSymbolAddress((void**)&rowlist, g_rowlist);
    cudaGetSymbolAddress((void**)&extlist, g_extlist);
    cudaGetSymbolAddress((void**)&totalp, g_total);
    cudaGetSymbolAddress((void**)&ext_totalp, g_ext_total);

    decode_mask_kernel<<<1, 256>>>(pm);

    // input projection: only rows that are ever read (masked + non-keep graphs)
    gemm64_kernel<<<dim3(NROWS / 64, 2), 128>>>(
        x, extlist, extlist, ext_totalp, W_in, W_in, b_in, b_in, h0, h0, DIN);

    for (int li = 0; li < 2; li++) {
        const float* hin = li ? hw : h0;                 // li=0: full+gather
        const int* rl = li ? nullptr : rowlist;          // li=1: compact direct
        gemm64_kernel<<<dim3(NROWS / 64, 4), 128>>>(
            hin, rl, nullptr, totalp, Wl + li * HID * HID, Wr + li * HID * HID,
            bl + li * HID, br + li * HID, xl, xr, HID);
        attn_kernel<<<dim3(NGRAPH, NHEAD, 2), 256>>>(xl, xr,
                                                     att + li * NHEAD * CH, go);
        epilogue_kernel<<<NROWS / 8, 256>>>(go, hw, h0, ob + li * HID,
                                            lns + li * HID, lnb + li * HID, hw,
                                            (li == 1) ? out : nullptr,
                                            (li == 1) ? 1 : 0);
    }
}

// round 16
// speedup vs baseline: 1.0921x; 1.0002x over previous
#include <cuda_runtime.h>
#include <cstdint>

#define HID 256
#define NNODE 64
#define NGRAPH 128
#define NROWS 8192   /* NGRAPH*NNODE */
#define DIN 512
#define NHEAD 4
#define CH 64

// ---------------- scratch (no allocations allowed -> __device__ globals) ----
__device__ float g_h0[NROWS * HID];   // projected input (full indexing, sparse fill)
__device__ float g_hw[NROWS * HID];   // working hidden state (COMPACT rows)
__device__ float g_xl[NROWS * HID];   // compact
__device__ float g_xr[NROWS * HID];   // compact
__device__ float g_go[NROWS * HID];   // gat raw output (compact)
__device__ unsigned long long g_maskbits[NGRAPH];
__device__ int g_keep[NGRAPH];
__device__ int g_rowlist[NROWS];      // compact -> full row index (masked rows)
__device__ int g_goff[NGRAPH + 1];    // per-graph compact offsets
__device__ int g_total;               // total masked rows
__device__ int g_extlist[NROWS];      // masked rows + rows of non-keep graphs
__device__ int g_ext_total;

// ---------------- f32x2 packed math (Blackwell FFMA2, PTX-only) -------------
#define PACK2(u, lo, hi) asm("mov.b64 %0, {%1, %2};" : "=l"(u) : "f"(lo), "f"(hi))
#define UNPACK2(lo, hi, u) asm("mov.b64 {%0, %1}, %2;" : "=f"(lo), "=f"(hi) : "l"(u))
#define FMA2ACC(d, a, b) asm("fma.rn.f32x2 %0, %1, %2, %0;" : "+l"(d) : "l"(a), "l"(b))
#define ADD2(d, a, b) asm("add.rn.f32x2 %0, %1, %2;" : "=l"(d) : "l"(a), "l"(b))

// ---------------- mask decode + compaction (dtype-robust) -------------------
__global__ void decode_mask_kernel(const unsigned char* __restrict__ pm) {
    __shared__ int flags[4];
    __shared__ unsigned char sm[NROWS];
    __shared__ unsigned long long s_mb[NGRAPH];
    __shared__ int s_cnt[NGRAPH];
    __shared__ int s_off[NGRAPH];
    __shared__ int s_eoff[NGRAPH];
    int tid = threadIdx.x;
    if (tid < 4) flags[tid] = 0;
    __syncthreads();
    int loc0 = 0, loc1 = 0, loc23 = 0;
    for (int i = tid; i < NROWS; i += 256) {
        if (pm[i]) {
            int r = i & 3;
            if (r == 0) loc0 = 1;
            else if (r == 1) loc1 = 1;
            else loc23 = 1;
        }
    }
    if (loc0) atomicOr(&flags[0], 1);
    if (loc1) atomicOr(&flags[1], 1);
    if (loc23) atomicOr(&flags[2], 1);
    __syncthreads();
    int mode;
    if (flags[1]) mode = 0;          // uint8
    else if (flags[0]) mode = 1;     // int32
    else if (flags[2]) mode = 2;     // float32
    else mode = 0;
    for (int i = tid; i < NROWS; i += 256) {
        unsigned char m;
        if (mode == 0)      m = (pm[i] != 0);
        else if (mode == 1) m = (((const int*)pm)[i] != 0);
        else                m = (((const float*)pm)[i] != 0.0f);
        sm[i] = m;
    }
    __syncthreads();
    if (tid < NGRAPH) {
        unsigned long long mb = 0ull;
        int cnt = 0;
        #pragma unroll
        for (int n = 0; n < 64; n++) {
            if (sm[tid * 64 + n]) { mb |= (1ull << n); cnt++; }
        }
        s_mb[tid] = mb;
        s_cnt[tid] = cnt;
        g_maskbits[tid] = mb;
        g_keep[tid] = (cnt > 1) ? 1 : 0;
    }
    __syncthreads();
    if (tid == 0) {
        int acc = 0, eacc = 0;
        for (int g2 = 0; g2 < NGRAPH; g2++) {
            s_off[g2] = acc;
            g_goff[g2] = acc;
            acc += s_cnt[g2];
            s_eoff[g2] = eacc;
            eacc += (s_cnt[g2] > 1) ? s_cnt[g2] : 64;   // non-keep: all rows
        }
        g_goff[NGRAPH] = acc;
        g_total = acc;
        g_ext_total = eacc;
    }
    __syncthreads();
    if (tid < NGRAPH) {
        int off = s_off[tid];
        unsigned long long b = s_mb[tid];
        int base = tid << 6;
        while (b) {
            g_rowlist[off++] = base + (__ffsll(b) - 1);
            b &= b - 1;
        }
        int eoff = s_eoff[tid];
        if (s_cnt[tid] > 1) {
            unsigned long long b2 = s_mb[tid];
            while (b2) {
                g_extlist[eoff++] = base + (__ffsll(b2) - 1);
                b2 &= b2 - 1;
            }
        } else {
            for (int n = 0; n < 64; n++) g_extlist[eoff++] = base + n;
        }
    }
}

// ---------------- GEMM: 64x128 tile, 128 threads, BK=8, 8x8 microtile -------
// (unchanged from R6 — conflict-free B columns, balanced 8:1 FFMA2:LDS)
__global__ __launch_bounds__(128, 4) void gemm64_kernel(
    const float* __restrict__ A, const int* __restrict__ rowlist,
    const int* __restrict__ outlist, const int* __restrict__ totalp,
    const float* __restrict__ W0, const float* __restrict__ W1,
    const float* __restrict__ bias0, const float* __restrict__ bias1,
    float* __restrict__ C0, float* __restrict__ C1, int K) {
    __shared__ float As[2][8][68];
    __shared__ float Bs[2][8][128];
    __shared__ int s_total;
    const int Nc = 256;
    int tid = threadIdx.x;
    if (tid == 0) s_total = totalp ? *totalp : NROWS;
    __syncthreads();
    int total = s_total;
    int bm = blockIdx.x << 6;
    if (bm >= total) return;

    int sel, bn;
    if (gridDim.y == 4) { sel = blockIdx.y >> 1; bn = (blockIdx.y & 1) << 7; }
    else               { sel = 0;               bn = blockIdx.y << 7; }
    const float* W = sel ? W1 : W0;
    const float* bias = sel ? bias1 : bias0;
    float* C = sel ? C1 : C0;

    int tx = tid & 15, ty = tid >> 4;
    int arow = tid >> 1, akq = (tid & 1) << 2;
    int r_glob = bm + arow;
    int ar = rowlist ? rowlist[min(r_glob, total - 1)] : r_glob;
    const float* Ag = A + (size_t)ar * K + akq;
    int brow0 = (tid >> 5) << 1, bcol = (tid & 31) << 2;
    const float* Bg = W + (size_t)brow0 * Nc + bn + bcol;

    unsigned long long acc[8][4];
    #pragma unroll
    for (int r = 0; r < 8; r++)
        #pragma unroll
        for (int p = 0; p < 4; p++) acc[r][p] = 0ull;

    float4 ra = *(const float4*)Ag;
    float4 rb0 = *(const float4*)Bg;
    float4 rb1 = *(const float4*)(Bg + Nc);
    As[0][akq + 0][arow] = ra.x;
    As[0][akq + 1][arow] = ra.y;
    As[0][akq + 2][arow] = ra.z;
    As[0][akq + 3][arow] = ra.w;
    *(float4*)&Bs[0][brow0][bcol] = rb0;
    *(float4*)&Bs[0][brow0 + 1][bcol] = rb1;
    __syncthreads();

    int KB = K >> 3;
    int s = 0;
    for (int kb = 0; kb < KB; kb++) {
        if (kb + 1 < KB) {
            ra = *(const float4*)(Ag + ((kb + 1) << 3));
            rb0 = *(const float4*)(Bg + (size_t)((kb + 1) << 3) * Nc);
            rb1 = *(const float4*)(Bg + (size_t)((kb + 1) << 3) * Nc + Nc);
        }
        #pragma unroll
        for (int k = 0; k < 8; k++) {
            float4 a0 = *(const float4*)&As[s][k][ty << 3];
            float4 a1 = *(const float4*)&As[s][k][(ty << 3) + 4];
            float4 b0 = *(const float4*)&Bs[s][k][tx << 2];
            float4 b1 = *(const float4*)&Bs[s][k][64 + (tx << 2)];
            unsigned long long bp0, bp1, bp2, bp3;
            PACK2(bp0, b0.x, b0.y); PACK2(bp1, b0.z, b0.w);
            PACK2(bp2, b1.x, b1.y); PACK2(bp3, b1.z, b1.w);
            unsigned long long ad[8];
            PACK2(ad[0], a0.x, a0.x); PACK2(ad[1], a0.y, a0.y);
            PACK2(ad[2], a0.z, a0.z); PACK2(ad[3], a0.w, a0.w);
            PACK2(ad[4], a1.x, a1.x); PACK2(ad[5], a1.y, a1.y);
            PACK2(ad[6], a1.z, a1.z); PACK2(ad[7], a1.w, a1.w);
            #pragma unroll
            for (int r = 0; r < 8; r++) {
                FMA2ACC(acc[r][0], ad[r], bp0);
                FMA2ACC(acc[r][1], ad[r], bp1);
                FMA2ACC(acc[r][2], ad[r], bp2);
                FMA2ACC(acc[r][3], ad[r], bp3);
            }
        }
        if (kb + 1 < KB) {
            int sn = s ^ 1;
            As[sn][akq + 0][arow] = ra.x;
            As[sn][akq + 1][arow] = ra.y;
            As[sn][akq + 2][arow] = ra.z;
            As[sn][akq + 3][arow] = ra.w;
            *(float4*)&Bs[sn][brow0][bcol] = rb0;
            *(float4*)&Bs[sn][brow0 + 1][bcol] = rb1;
            __syncthreads();
            s = sn;
        }
    }

    float4 bb0 = *(const float4*)(bias + bn + (tx << 2));
    float4 bb1 = *(const float4*)(bias + bn + 64 + (tx << 2));
    #pragma unroll
    for (int r = 0; r < 8; r++) {
        int crow = bm + (ty << 3) + r;
        if (crow < total) {
            int orow = outlist ? outlist[crow] : crow;
            float* cp = C + (size_t)orow * Nc + bn;
            float4 o0, o1;
            UNPACK2(o0.x, o0.y, acc[r][0]); UNPACK2(o0.z, o0.w, acc[r][1]);
            UNPACK2(o1.x, o1.y, acc[r][2]); UNPACK2(o1.z, o1.w, acc[r][3]);
            o0.x += bb0.x; o0.y += bb0.y; o0.z += bb0.z; o0.w += bb0.w;
            o1.x += bb1.x; o1.y += bb1.y; o1.z += bb1.z; o1.w += bb1.w;
            *(float4*)(cp + (tx << 2)) = o0;
            *(float4*)(cp + 64 + (tx << 2)) = o1;
        }
    }
}

// ---------------- GATv2 attention, z-split x2 over target rows --------------
// grid (NGRAPH, NHEAD, 2): 16 virtual warps own rows mi === vw (mod 16),
// pairs (mi0, mi0+16), stride 32. float4 tile loads.
__global__ __launch_bounds__(256) void attn_kernel(
    const float* __restrict__ xl, const float* __restrict__ xr,
    const float* __restrict__ att, float* __restrict__ go) {
    __shared__ float s_xlc[64 * 64];
    __shared__ float s_xrc[64 * 64];
    __shared__ float s_alpha[8][2][64];
    __shared__ float s_att[64];
    __shared__ float s_dl[64], s_dr[64];

    int g = blockIdx.x, h = blockIdx.y;
    int tid = threadIdx.x, w = tid >> 5, l = tid & 31;
    int vw = (blockIdx.z << 3) + w;   // 0..15
    int goffg = g_goff[g];
    int M = g_goff[g + 1] - goffg;
    if (M == 0) return;
    int hoff = h << 6;

    if (tid < 64) s_att[tid] = att[hoff + tid];
    for (int idx4 = tid; idx4 < (M << 4); idx4 += 256) {
        int m = idx4 >> 4, c4 = (idx4 & 15) << 2;
        size_t p = (size_t)(goffg + m) * HID + hoff + c4;
        *(float4*)&s_xlc[(m << 6) + c4] = *(const float4*)(xl + p);
        *(float4*)&s_xrc[(m << 6) + c4] = *(const float4*)(xr + p);
    }
    __syncthreads();

    // per-node rank-1 dots (skewed c -> conflict-free)
    if (tid < M) {
        float dl = 0.f, dr = 0.f;
        #pragma unroll 8
        for (int t = 0; t < 64; t++) {
            int c = (t + tid) & 63;
            float a = s_att[c];
            dl = fmaf(a, s_xlc[(tid << 6) + c], dl);
            dr = fmaf(a, s_xrc[(tid << 6) + c], dr);
        }
        s_dl[tid] = dl;
        s_dr[tid] = dr;
    }
    __syncthreads();

    const unsigned long long ABS2 = 0x7FFFFFFF7FFFFFFFull;
    bool v1 = (l < M), v2 = (l + 32 < M);
    float dl1 = v1 ? s_dl[l] : 0.f;
    float dl2 = v2 ? s_dl[l + 32] : 0.f;

    for (int mi0 = vw; mi0 < M; mi0 += 32) {
        int miA = mi0;
        int miB = (mi0 + 16) & 63;       // may be dead: computed, discarded
        bool hasB = (mi0 + 16) < M;
        unsigned long long aA1 = 0ull, aA2 = 0ull, aB1 = 0ull, aB2 = 0ull;
        #pragma unroll 4
        for (int t = 0; t < 32; t++) {
            int c = ((t + l) & 31) << 1;   // skew -> conflict-free 64-bit LDS
            unsigned long long a2 = *(const unsigned long long*)&s_att[c];
            unsigned long long x1 = *(const unsigned long long*)&s_xlc[(l << 6) + c];
            unsigned long long x2 = *(const unsigned long long*)&s_xlc[((l + 32) << 6) + c];
            unsigned long long rA = *(const unsigned long long*)&s_xrc[(miA << 6) + c];
            unsigned long long rB = *(const unsigned long long*)&s_xrc[(miB << 6) + c];
            unsigned long long sA1, sA2, sB1, sB2;
            ADD2(sA1, rA, x1); ADD2(sA2, rA, x2);
            ADD2(sB1, rB, x1); ADD2(sB2, rB, x2);
            sA1 &= ABS2; sA2 &= ABS2; sB1 &= ABS2; sB2 &= ABS2;
            FMA2ACC(aA1, a2, sA1); FMA2ACC(aA2, a2, sA2);
            FMA2ACC(aB1, a2, sB1); FMA2ACC(aB2, a2, sB2);
        }
        float lo, hi;
        UNPACK2(lo, hi, aA1); float abA1 = lo + hi;
        UNPACK2(lo, hi, aA2); float abA2 = lo + hi;
        UNPACK2(lo, hi, aB1); float abB1 = lo + hi;
        UNPACK2(lo, hi, aB2); float abB2 = lo + hi;
        float drA = s_dr[miA];
        float drB = s_dr[miB];
        float eA1 = v1 ? fmaf(0.4f, abA1, 0.6f * (drA + dl1)) : -1e30f;
        float eA2 = v2 ? fmaf(0.4f, abA2, 0.6f * (drA + dl2)) : -1e30f;
        float eB1 = v1 ? fmaf(0.4f, abB1, 0.6f * (drB + dl1)) : -1e30f;
        float eB2 = v2 ? fmaf(0.4f, abB2, 0.6f * (drB + dl2)) : -1e30f;
        float mxA = fmaxf(eA1, eA2);
        float mxB = fmaxf(eB1, eB2);
        #pragma unroll
        for (int o = 16; o > 0; o >>= 1) {
            mxA = fmaxf(mxA, __shfl_xor_sync(0xffffffffu, mxA, o));
            mxB = fmaxf(mxB, __shfl_xor_sync(0xffffffffu, mxB, o));
        }
        float pA1 = expf(eA1 - mxA), pA2 = expf(eA2 - mxA);
        float pB1 = expf(eB1 - mxB), pB2 = expf(eB2 - mxB);
        float svA = pA1 + pA2, svB = pB1 + pB2;
        #pragma unroll
        for (int o = 16; o > 0; o >>= 1) {
            svA += __shfl_xor_sync(0xffffffffu, svA, o);
            svB += __shfl_xor_sync(0xffffffffu, svB, o);
        }
        float invA = 1.0f / svA, invB = 1.0f / svB;
        s_alpha[w][0][l] = pA1 * invA;
        s_alpha[w][0][l + 32] = pA2 * invA;
        s_alpha[w][1][l] = pB1 * invB;
        s_alpha[w][1][l + 32] = pB2 * invB;
        __syncwarp();

        float oA1 = 0.f, oA2 = 0.f, oB1 = 0.f, oB2 = 0.f;
        for (int mj = 0; mj < M; mj++) {
            float x1 = s_xlc[(mj << 6) + l];
            float x2 = s_xlc[(mj << 6) + l + 32];
            float alA = s_alpha[w][0][mj];
            float alB = s_alpha[w][1][mj];
            oA1 = fmaf(alA, x1, oA1);
            oA2 = fmaf(alA, x2, oA2);
            oB1 = fmaf(alB, x1, oB1);
            oB2 = fmaf(alB, x2, oB2);
        }
        size_t gA = (size_t)(goffg + miA) * HID + hoff;
        go[gA + l] = oA1;
        go[gA + l + 32] = oA2;
        if (hasB) {
            size_t gB = (size_t)(goffg + miB) * HID + hoff;
            go[gB + l] = oB1;
            go[gB + l + 32] = oB2;
        }
        __syncwarp();
    }
}

// ---------------- epilogue: warp-per-row, shfl-only LN ----------------------
__device__ __forceinline__ float warp_sum(float v) {
    #pragma unroll
    for (int o = 16; o > 0; o >>= 1)
        v += __shfl_xor_sync(0xffffffffu, v, o);
    return v;
}

__global__ __launch_bounds__(256) void epilogue_kernel(
    const float* __restrict__ go_c, const float* __restrict__ hw_c_in,
    const float* __restrict__ h0,
    const float* __restrict__ ob, const float* __restrict__ lns,
    const float* __restrict__ lnb,
    float* __restrict__ hw_c_out, float* __restrict__ outp, int final_layer) {
    int tid = threadIdx.x;
    int w = tid >> 5, l = tid & 31;
    int row = (blockIdx.x << 3) + w;     // full row, one warp each
    int g = row >> 6, node = row & 63;
    unsigned long long mb = g_maskbits[g];
    bool masked = (mb >> node) & 1ull;
    int cb = l << 3;                     // 8 channels per lane
    size_t fbase = (size_t)row * HID + cb;

    if (final_layer && !g_keep[g]) {
        *(float4*)(outp + fbase) = *(const float4*)(h0 + fbase);
        *(float4*)(outp + fbase + 4) = *(const float4*)(h0 + fbase + 4);
        return;
    }
    if (!masked) {
        if (final_layer) {
            float4 z = make_float4(0.f, 0.f, 0.f, 0.f);
            *(float4*)(outp + fbase) = z;
            *(float4*)(outp + fbase + 4) = z;
        }
        return;
    }
    int ci = g_goff[g] + (int)__popcll(mb & ((1ull << node) - 1ull));
    size_t cbase = (size_t)ci * HID + cb;

    float v[8];
    {
        float4 g0 = *(const float4*)(go_c + cbase);
        float4 g1 = *(const float4*)(go_c + cbase + 4);
        float4 o0 = *(const float4*)(ob + cb);
        float4 o1 = *(const float4*)(ob + cb + 4);
        v[0] = g0.x + o0.x; v[1] = g0.y + o0.y;
        v[2] = g0.z + o0.z; v[3] = g0.w + o0.w;
        v[4] = g1.x + o1.x; v[5] = g1.y + o1.y;
        v[6] = g1.z + o1.z; v[7] = g1.w + o1.w;
    }
    #pragma unroll
    for (int i = 0; i < 8; i++)
        v[i] = (v[i] > 0.f) ? v[i] : expm1f(v[i]);     // ELU (alpha=1)

    float loc = 0.f;
    #pragma unroll
    for (int i = 0; i < 8; i++) loc += v[i];
    float mu = warp_sum(loc) * (1.0f / 256.0f);

    float d[8], s2 = 0.f;
    #pragma unroll
    for (int i = 0; i < 8; i++) { d[i] = v[i] - mu; s2 = fmaf(d[i], d[i], s2); }
    float var = warp_sum(s2) * (1.0f / 256.0f);
    float rstd = rsqrtf(var + 1e-5f);

    float4 s0 = *(const float4*)(lns + cb);
    float4 s1 = *(const float4*)(lns + cb + 4);
    float4 b0 = *(const float4*)(lnb + cb);
    float4 b1 = *(const float4*)(lnb + cb + 4);
    float4 r0, r1;
    if (final_layer) {
        r0 = *(const float4*)(hw_c_in + cbase);
        r1 = *(const float4*)(hw_c_in + cbase + 4);
    } else {
        r0 = *(const float4*)(h0 + fbase);
        r1 = *(const float4*)(h0 + fbase + 4);
    }
    float4 y0, y1;
    y0.x = fmaf(d[0] * rstd, s0.x, b0.x) + r0.x;
    y0.y = fmaf(d[1] * rstd, s0.y, b0.y) + r0.y;
    y0.z = fmaf(d[2] * rstd, s0.z, b0.z) + r0.z;
    y0.w = fmaf(d[3] * rstd, s0.w, b0.w) + r0.w;
    y1.x = fmaf(d[4] * rstd, s1.x, b1.x) + r1.x;
    y1.y = fmaf(d[5] * rstd, s1.y, b1.y) + r1.y;
    y1.z = fmaf(d[6] * rstd, s1.z, b1.z) + r1.z;
    y1.w = fmaf(d[7] * rstd, s1.w, b1.w) + r1.w;
    if (final_layer) {
        *(float4*)(outp + fbase) = y0;
        *(float4*)(outp + fbase + 4) = y1;
    } else {
        *(float4*)(hw_c_out + cbase) = y0;
        *(float4*)(hw_c_out + cbase + 4) = y1;
    }
}

// ---------------- launch ----------------------------------------------------
extern "C" void kernel_launch(void* const* d_in, const int* in_sizes, int n_in,
                              void* d_out, int out_size) {
    (void)in_sizes; (void)n_in; (void)out_size;
    const float* x   = (const float*)d_in[0];
    const unsigned char* pm = (const unsigned char*)d_in[1];
    const float* W_in = (const float*)d_in[2];
    const float* b_in = (const float*)d_in[3];
    const float* Wl  = (const float*)d_in[4];
    const float* bl  = (const float*)d_in[5];
    const float* Wr  = (const float*)d_in[6];
    const float* br  = (const float*)d_in[7];
    const float* att = (const float*)d_in[8];
    const float* ob  = (const float*)d_in[9];
    const float* lns = (const float*)d_in[10];
    const float* lnb = (const float*)d_in[11];
    float* out = (float*)d_out;

    float *h0, *hw, *xl, *xr, *go;
    int *rowlist, *extlist, *totalp, *ext_totalp;
    cudaGetSymbolAddress((void**)&h0, g_h0);
    cudaGetSymbolAddress((void**)&hw, g_hw);
    cudaGetSymbolAddress((void**)&xl, g_xl);
    cudaGetSymbolAddress((void**)&xr, g_xr);
    cudaGetSymbolAddress((void**)&go, g_go);
    cudaGetSymbolAddress((void**)&rowlist, g_rowlist);
    cudaGetSymbolAddress((void**)&extlist, g_extlist);
    cudaGetSymbolAddress((void**)&totalp, g_total);
    cudaGetSymbolAddress((void**)&ext_totalp, g_ext_total);

    decode_mask_kernel<<<1, 256>>>(pm);

    // input projection: only rows that are ever read (masked + non-keep graphs)
    gemm64_kernel<<<dim3(NROWS / 64, 2), 128>>>(
        x, extlist, extlist, ext_totalp, W_in, W_in, b_in, b_in, h0, h0, DIN);

    for (int li = 0; li < 2; li++) {
        const float* hin = li ? hw : h0;                 // li=0: full+gather
        const int* rl = li ? nullptr : rowlist;          // li=1: compact direct
        gemm64_kernel<<<dim3(NROWS / 64, 4), 128>>>(
            hin, rl, nullptr, totalp, Wl + li * HID * HID, Wr + li * HID * HID,
            bl + li * HID, br + li * HID, xl, xr, HID);
        attn_kernel<<<dim3(NGRAPH, NHEAD, 2), 256>>>(xl, xr,
                                                     att + li * NHEAD * CH, go);
        epilogue_kernel<<<NROWS / 8, 256>>>(go, hw, h0, ob + li * HID,
                                            lns + li * HID, lnb + li * HID, hw,
                                            (li == 1) ? out : nullptr,
                                            (li == 1) ? 1 : 0);
    }
}